// round 2
// baseline (speedup 1.0000x reference)
#include <cuda_runtime.h>
#include <cuda_bf16.h>
#include <cstdint>

// Problem constants
#define B_DIM   32
#define C_DIM   256
#define HW_DIM  1024
#define NVEC    32768            // B*HW
#define KCODES  1024
#define NTOT    8388608          // NVEC * C_DIM  (z_q element count)

// Scratch (device globals — no allocation allowed)
__device__ int   g_idx[NVEC];
__device__ float g_cn[KCODES];      // ||c_k||^2  (FULL norm, to match reference formula)
__device__ float g_zn[NVEC];        // ||z_n||^2
__device__ float g_part[1024];      // per-block loss partials

typedef unsigned long long u64t;

// Packed fp32x2 FMA (Blackwell FFMA2) — 2x fp32 throughput vs scalar FFMA
__device__ __forceinline__ void fma2(u64t& d, u64t a, u64t b) {
    asm("fma.rn.f32x2 %0, %1, %2, %0;" : "+l"(d) : "l"(a), "l"(b));
}

// ---------------------------------------------------------------------------
// Kernel 0a: full squared norms of codebook rows
// ---------------------------------------------------------------------------
__global__ void cnorm_kernel(const float* __restrict__ cb)
{
    int k = blockIdx.x * 256 + threadIdx.x;   // grid 4 x 256 = 1024
    const float* row = cb + (size_t)k * C_DIM;
    float s = 0.f;
#pragma unroll 8
    for (int i = 0; i < C_DIM; i++) { float c = row[i]; s += c * c; }
    g_cn[k] = s;
}

// ---------------------------------------------------------------------------
// Kernel 0b: squared norms of z vectors. n=(b,hw); channels strided by HW.
// ---------------------------------------------------------------------------
__global__ void znorm_kernel(const float* __restrict__ z)
{
    int n  = blockIdx.x * 256 + threadIdx.x;  // grid 128 x 256 = 32768
    int b  = n >> 10;
    int hw = n & 1023;
    const float* p = z + (size_t)b * (C_DIM * HW_DIM) + hw;
    float s = 0.f;
#pragma unroll 8
    for (int c = 0; c < C_DIM; c++) { float v = p[(size_t)c << 10]; s += v * v; }
    g_zn[n] = s;
}

// ---------------------------------------------------------------------------
// Kernel 1: fused fp32 GEMM + argmin, replicating the REFERENCE rounding:
//   d(n,k) = fl32( fl32(||z_n||^2 - 2*dot) + ||c_k||^2 ),  argmin_k, ties -> lowest k.
//   The (||z||^2 - 2dot) add quantizes d to ulp(~256)=3e-5; near-ties must be
//   resolved exactly as the reference does, hence the faithful formula.
//   BM=64 rows/CTA, BN=128 codes/tile (8 tiles), BK=16, 128 threads.
// ---------------------------------------------------------------------------
__global__ __launch_bounds__(128, 4)
void argmin_kernel(const float* __restrict__ z, const float* __restrict__ cb)
{
    __shared__ float AsD[16][136];     // duplicated A: [BK][2*BM + pad]
    __shared__ float Bs [16][132];     // [BK][BN + pad]
    __shared__ float cn_s[128];
    __shared__ float redV[64][17];
    __shared__ int   redI[64][17];

    const int tid = threadIdx.x;
    const int tx  = tid & 15;
    const int ty  = tid >> 4;

    const int rowBase = blockIdx.x * 64;          // 512 CTAs
    const int b   = rowBase >> 10;
    const int hw0 = rowBase & 1023;               // 64 | 1024 -> single b per tile
    const float* zb = z + (size_t)b * (C_DIM * HW_DIM) + hw0;

    // per-thread z-norms for its 8 rows (L2-cached, tiny)
    float znr[8];
#pragma unroll
    for (int r = 0; r < 8; r++) znr[r] = g_zn[rowBase + ty * 8 + r];

    float bestV[8];
    int   bestI[8];
#pragma unroll
    for (int r = 0; r < 8; r++) { bestV[r] = 3.4e38f; bestI[r] = 0; }

    for (int kt = 0; kt < 8; kt++) {
        const int k0 = kt * 128;
        if (tid < 128) cn_s[tid] = g_cn[k0 + tid];

        u64t acc[8][4];
#pragma unroll
        for (int r = 0; r < 8; r++)
#pragma unroll
            for (int j = 0; j < 4; j++) acc[r][j] = 0ull;

        for (int ck = 0; ck < 16; ck++) {
            __syncthreads();   // protect smem from previous iter readers
            // ---- A fill (duplicate each value: (x,x,y,y,...)), coalesced f4 loads
#pragma unroll
            for (int it = 0; it < 2; it++) {
                int v  = it * 128 + tid;
                int c  = v >> 4;          // 0..15
                int mq = v & 15;          // *4 -> m
                float4 f = *(const float4*)(zb + (size_t)(ck * 16 + c) * HW_DIM + mq * 4);
                float* d = &AsD[c][mq * 8];
                ((float4*)d)[0] = make_float4(f.x, f.x, f.y, f.y);
                ((float4*)d)[1] = make_float4(f.z, f.z, f.w, f.w);
            }
            // ---- B fill (transpose codebook rows into [c][j])
#pragma unroll
            for (int it = 0; it < 4; it++) {
                int v  = it * 128 + tid;
                int j  = v >> 2;          // 0..127
                int cq = (v & 3) * 4;     // 0,4,8,12
                float4 f = *(const float4*)(cb + (size_t)(k0 + j) * C_DIM + ck * 16 + cq);
                Bs[cq + 0][j] = f.x;
                Bs[cq + 1][j] = f.y;
                Bs[cq + 2][j] = f.z;
                Bs[cq + 3][j] = f.w;
            }
            __syncthreads();
            // ---- compute: 16 c-steps, 32 FMA2 (=64 fp32 FMA) per thread per step
#pragma unroll
            for (int c = 0; c < 16; c++) {
                u64t a2[8], b2[4];
#pragma unroll
                for (int r = 0; r < 8; r++)
                    a2[r] = *(const u64t*)&AsD[c][(ty * 8 + r) * 2];
#pragma unroll
                for (int j = 0; j < 4; j++)
                    b2[j] = *(const u64t*)&Bs[c][2 * tx + 32 * j];
#pragma unroll
                for (int r = 0; r < 8; r++)
#pragma unroll
                    for (int j = 0; j < 4; j++)
                        fma2(acc[r][j], a2[r], b2[j]);
            }
        }
        // ---- epilogue: d = fl(fl(Zn - 2*dot) + cn); running argmin.
        //      k processed ascending; strict '<' keeps the lowest index on ties
        //      (matches jnp.argmin first-occurrence rule).
#pragma unroll
        for (int j = 0; j < 4; j++) {
            int   kloc = 2 * tx + 32 * j;
            float cn0  = cn_s[kloc];
            float cn1  = cn_s[kloc + 1];
            int   kg   = k0 + kloc;
#pragma unroll
            for (int r = 0; r < 8; r++) {
                float lo = __uint_as_float((unsigned)(acc[r][j] & 0xffffffffull));
                float hi = __uint_as_float((unsigned)(acc[r][j] >> 32));
                float d0 = (znr[r] - 2.0f * lo) + cn0;   // two fp32 roundings, as reference
                float d1 = (znr[r] - 2.0f * hi) + cn1;
                if (d0 < bestV[r]) { bestV[r] = d0; bestI[r] = kg; }
                if (d1 < bestV[r]) { bestV[r] = d1; bestI[r] = kg + 1; }
            }
        }
        __syncthreads();   // cn_s write-after-read fence for next tile
    }

    // ---- cross-thread (16 tx) reduction per row, tie-break = lower k
#pragma unroll
    for (int r = 0; r < 8; r++) {
        redV[ty * 8 + r][tx] = bestV[r];
        redI[ty * 8 + r][tx] = bestI[r];
    }
    __syncthreads();
    if (tid < 64) {
        float bv = redV[tid][0];
        int   bi = redI[tid][0];
#pragma unroll
        for (int t = 1; t < 16; t++) {
            float v = redV[tid][t];
            int   i = redI[tid][t];
            if (v < bv || (v == bv && i < bi)) { bv = v; bi = i; }
        }
        g_idx[rowBase + tid] = bi;
    }
}

// ---------------------------------------------------------------------------
// Kernel 2: gather codebook rows -> [B,C,H,W] output with straight-through
//           rounding (out = z + (q - z)) + per-block loss partial sums.
//   Block = 32 vectors (same b, contiguous hw). 1024 blocks x 256 threads.
// ---------------------------------------------------------------------------
__global__ void gather_kernel(const float* __restrict__ z,
                              const float* __restrict__ cb,
                              float* __restrict__ out)
{
    __shared__ int   sidx[32];
    __shared__ float cbs[32][257];    // pad 257 -> conflict-free column reads
    __shared__ float ws[8];

    const int tid = threadIdx.x;
    const int v0  = blockIdx.x * 32;
    const int b   = v0 >> 10;
    const int hw0 = v0 & 1023;

    if (tid < 32) sidx[tid] = g_idx[v0 + tid];
    __syncthreads();
#pragma unroll 4
    for (int i = 0; i < 32; i++)
        cbs[i][tid] = cb[(size_t)sidx[i] * C_DIM + tid];   // coalesced row loads
    __syncthreads();

    const size_t base = (size_t)b * (C_DIM * HW_DIM) + hw0;
    float lsum = 0.f;
#pragma unroll 4
    for (int it = 0; it < 32; it++) {
        int u = it * 256 + tid;
        int m = u & 31;          // hw offset   (lanes -> coalesced 128B)
        int c = u >> 5;          // channel
        size_t g = base + (size_t)c * HW_DIM + m;
        float q  = cbs[m][c];
        float zv = z[g];
        float d  = q - zv;
        out[g] = zv + d;         // match reference's straight-through rounding
        lsum  += d * d;
    }
    // deterministic in-block reduction
#pragma unroll
    for (int off = 16; off; off >>= 1)
        lsum += __shfl_down_sync(0xffffffffu, lsum, off);
    if ((tid & 31) == 0) ws[tid >> 5] = lsum;
    __syncthreads();
    if (tid == 0) {
        float t = 0.f;
#pragma unroll
        for (int w = 0; w < 8; w++) t += ws[w];
        g_part[blockIdx.x] = t;
    }
}

// ---------------------------------------------------------------------------
// Kernel 3: deterministic final loss reduction; loss = 1.25 * mean(d^2)
// ---------------------------------------------------------------------------
__global__ void finalize_kernel(float* __restrict__ out, int out_size)
{
    __shared__ float s[256];
    __shared__ float lossS;
    const int tid = threadIdx.x;
    float v = 0.f;
#pragma unroll
    for (int j = 0; j < 4; j++) v += g_part[tid + j * 256];
    s[tid] = v;
    __syncthreads();
    for (int o = 128; o > 0; o >>= 1) {
        if (tid < o) s[tid] += s[tid + o];
        __syncthreads();
    }
    if (tid == 0) lossS = s[0] * (1.25f / 8388608.0f);
    __syncthreads();
    for (int i = NTOT + tid; i < out_size; i += 256) out[i] = lossS;
}

// ---------------------------------------------------------------------------
extern "C" void kernel_launch(void* const* d_in, const int* in_sizes, int n_in,
                              void* d_out, int out_size)
{
    const float* z  = (const float*)d_in[0];
    const float* cb = (const float*)d_in[1];
    if (n_in >= 2 && in_sizes[0] == KCODES * C_DIM && in_sizes[1] == NTOT) {
        // defensive: swapped input order
        const float* t = z; z = cb; cb = t;
    }
    float* out = (float*)d_out;

    cnorm_kernel   <<<4,    256>>>(cb);
    znorm_kernel   <<<128,  256>>>(z);
    argmin_kernel  <<<512,  128>>>(z, cb);
    gather_kernel  <<<1024, 256>>>(z, cb, out);
    finalize_kernel<<<1,    256>>>(out, out_size);
}

// round 3
// speedup vs baseline: 1.0011x; 1.0011x over previous
#include <cuda_runtime.h>
#include <cuda_bf16.h>
#include <cstdint>

// Problem constants
#define B_DIM   32
#define C_DIM   256
#define HW_DIM  1024
#define NVEC    32768            // B*HW
#define KCODES  1024
#define NTOT    8388608          // NVEC * C_DIM  (z_q element count)

// Scratch (device globals — no allocation allowed)
__device__ int   g_idx[NVEC];
__device__ float g_cn[KCODES];      // ||c_k||^2  (FULL norm, to match reference formula)
__device__ float g_zn[NVEC];        // ||z_n||^2
__device__ float g_part[1024];      // per-block loss partials

typedef unsigned long long u64t;

// Packed fp32x2 FMA (Blackwell FFMA2) — 2x fp32 throughput vs scalar FFMA
__device__ __forceinline__ void fma2(u64t& d, u64t a, u64t b) {
    asm("fma.rn.f32x2 %0, %1, %2, %0;" : "+l"(d) : "l"(a), "l"(b));
}

// ---------------------------------------------------------------------------
// Kernel 0a: full squared norms of codebook rows
// ---------------------------------------------------------------------------
__global__ void cnorm_kernel(const float* __restrict__ cb)
{
    int k = blockIdx.x * 256 + threadIdx.x;   // grid 4 x 256 = 1024
    const float* row = cb + (size_t)k * C_DIM;
    float s = 0.f;
#pragma unroll 8
    for (int i = 0; i < C_DIM; i++) { float c = row[i]; s += c * c; }
    g_cn[k] = s;
}

// ---------------------------------------------------------------------------
// Kernel 0b: squared norms of z vectors. n=(b,hw); channels strided by HW.
// ---------------------------------------------------------------------------
__global__ void znorm_kernel(const float* __restrict__ z)
{
    int n  = blockIdx.x * 256 + threadIdx.x;  // grid 128 x 256 = 32768
    int b  = n >> 10;
    int hw = n & 1023;
    const float* p = z + (size_t)b * (C_DIM * HW_DIM) + hw;
    float s = 0.f;
#pragma unroll 8
    for (int c = 0; c < C_DIM; c++) { float v = p[(size_t)c << 10]; s += v * v; }
    g_zn[n] = s;
}

// ---------------------------------------------------------------------------
// Kernel 1: fused fp32 GEMM + argmin, replicating the REFERENCE rounding:
//   d(n,k) = fl32( fl32(||z_n||^2 - 2*dot) + ||c_k||^2 ),  argmin_k, ties -> lowest k.
//   The (||z||^2 - 2dot) add quantizes d to ulp(~256)=3e-5; near-ties must be
//   resolved exactly as the reference does, hence the faithful formula.
//   BM=64 rows/CTA, BN=128 codes/tile (8 tiles), BK=16, 128 threads.
// ---------------------------------------------------------------------------
__global__ __launch_bounds__(128, 4)
void argmin_kernel(const float* __restrict__ z, const float* __restrict__ cb)
{
    __shared__ float AsD[16][136];     // duplicated A: [BK][2*BM + pad]
    __shared__ float Bs [16][132];     // [BK][BN + pad]
    __shared__ float cn_s[128];
    __shared__ float redV[64][17];
    __shared__ int   redI[64][17];

    const int tid = threadIdx.x;
    const int tx  = tid & 15;
    const int ty  = tid >> 4;

    const int rowBase = blockIdx.x * 64;          // 512 CTAs
    const int b   = rowBase >> 10;
    const int hw0 = rowBase & 1023;               // 64 | 1024 -> single b per tile
    const float* zb = z + (size_t)b * (C_DIM * HW_DIM) + hw0;

    // per-thread z-norms for its 8 rows (L2-cached, tiny)
    float znr[8];
#pragma unroll
    for (int r = 0; r < 8; r++) znr[r] = g_zn[rowBase + ty * 8 + r];

    float bestV[8];
    int   bestI[8];
#pragma unroll
    for (int r = 0; r < 8; r++) { bestV[r] = 3.4e38f; bestI[r] = 0; }

    for (int kt = 0; kt < 8; kt++) {
        const int k0 = kt * 128;
        if (tid < 128) cn_s[tid] = g_cn[k0 + tid];

        u64t acc[8][4];
#pragma unroll
        for (int r = 0; r < 8; r++)
#pragma unroll
            for (int j = 0; j < 4; j++) acc[r][j] = 0ull;

        for (int ck = 0; ck < 16; ck++) {
            __syncthreads();   // protect smem from previous iter readers
            // ---- A fill (duplicate each value: (x,x,y,y,...)), coalesced f4 loads
#pragma unroll
            for (int it = 0; it < 2; it++) {
                int v  = it * 128 + tid;
                int c  = v >> 4;          // 0..15
                int mq = v & 15;          // *4 -> m
                float4 f = *(const float4*)(zb + (size_t)(ck * 16 + c) * HW_DIM + mq * 4);
                float* d = &AsD[c][mq * 8];
                ((float4*)d)[0] = make_float4(f.x, f.x, f.y, f.y);
                ((float4*)d)[1] = make_float4(f.z, f.z, f.w, f.w);
            }
            // ---- B fill (transpose codebook rows into [c][j])
#pragma unroll
            for (int it = 0; it < 4; it++) {
                int v  = it * 128 + tid;
                int j  = v >> 2;          // 0..127
                int cq = (v & 3) * 4;     // 0,4,8,12
                float4 f = *(const float4*)(cb + (size_t)(k0 + j) * C_DIM + ck * 16 + cq);
                Bs[cq + 0][j] = f.x;
                Bs[cq + 1][j] = f.y;
                Bs[cq + 2][j] = f.z;
                Bs[cq + 3][j] = f.w;
            }
            __syncthreads();
            // ---- compute: 16 c-steps, 32 FMA2 (=64 fp32 FMA) per thread per step
#pragma unroll
            for (int c = 0; c < 16; c++) {
                u64t a2[8], b2[4];
#pragma unroll
                for (int r = 0; r < 8; r++)
                    a2[r] = *(const u64t*)&AsD[c][(ty * 8 + r) * 2];
#pragma unroll
                for (int j = 0; j < 4; j++)
                    b2[j] = *(const u64t*)&Bs[c][2 * tx + 32 * j];
#pragma unroll
                for (int r = 0; r < 8; r++)
#pragma unroll
                    for (int j = 0; j < 4; j++)
                        fma2(acc[r][j], a2[r], b2[j]);
            }
        }
        // ---- epilogue: d = fl(fl(Zn - 2*dot) + cn); running argmin.
        //      k processed ascending; strict '<' keeps the lowest index on ties
        //      (matches jnp.argmin first-occurrence rule).
#pragma unroll
        for (int j = 0; j < 4; j++) {
            int   kloc = 2 * tx + 32 * j;
            float cn0  = cn_s[kloc];
            float cn1  = cn_s[kloc + 1];
            int   kg   = k0 + kloc;
#pragma unroll
            for (int r = 0; r < 8; r++) {
                float lo = __uint_as_float((unsigned)(acc[r][j] & 0xffffffffull));
                float hi = __uint_as_float((unsigned)(acc[r][j] >> 32));
                float d0 = (znr[r] - 2.0f * lo) + cn0;   // two fp32 roundings, as reference
                float d1 = (znr[r] - 2.0f * hi) + cn1;
                if (d0 < bestV[r]) { bestV[r] = d0; bestI[r] = kg; }
                if (d1 < bestV[r]) { bestV[r] = d1; bestI[r] = kg + 1; }
            }
        }
        __syncthreads();   // cn_s write-after-read fence for next tile
    }

    // ---- cross-thread (16 tx) reduction per row, tie-break = lower k
#pragma unroll
    for (int r = 0; r < 8; r++) {
        redV[ty * 8 + r][tx] = bestV[r];
        redI[ty * 8 + r][tx] = bestI[r];
    }
    __syncthreads();
    if (tid < 64) {
        float bv = redV[tid][0];
        int   bi = redI[tid][0];
#pragma unroll
        for (int t = 1; t < 16; t++) {
            float v = redV[tid][t];
            int   i = redI[tid][t];
            if (v < bv || (v == bv && i < bi)) { bv = v; bi = i; }
        }
        g_idx[rowBase + tid] = bi;
    }
}

// ---------------------------------------------------------------------------
// Kernel 2: gather codebook rows -> [B,C,H,W] output with straight-through
//           rounding (out = z + (q - z)) + per-block loss partial sums.
//   Block = 32 vectors (same b, contiguous hw). 1024 blocks x 256 threads.
// ---------------------------------------------------------------------------
__global__ void gather_kernel(const float* __restrict__ z,
                              const float* __restrict__ cb,
                              float* __restrict__ out)
{
    __shared__ int   sidx[32];
    __shared__ float cbs[32][257];    // pad 257 -> conflict-free column reads
    __shared__ float ws[8];

    const int tid = threadIdx.x;
    const int v0  = blockIdx.x * 32;
    const int b   = v0 >> 10;
    const int hw0 = v0 & 1023;

    if (tid < 32) sidx[tid] = g_idx[v0 + tid];
    __syncthreads();
#pragma unroll 4
    for (int i = 0; i < 32; i++)
        cbs[i][tid] = cb[(size_t)sidx[i] * C_DIM + tid];   // coalesced row loads
    __syncthreads();

    const size_t base = (size_t)b * (C_DIM * HW_DIM) + hw0;
    float lsum = 0.f;
#pragma unroll 4
    for (int it = 0; it < 32; it++) {
        int u = it * 256 + tid;
        int m = u & 31;          // hw offset   (lanes -> coalesced 128B)
        int c = u >> 5;          // channel
        size_t g = base + (size_t)c * HW_DIM + m;
        float q  = cbs[m][c];
        float zv = z[g];
        float d  = q - zv;
        out[g] = zv + d;         // match reference's straight-through rounding
        lsum  += d * d;
    }
    // deterministic in-block reduction
#pragma unroll
    for (int off = 16; off; off >>= 1)
        lsum += __shfl_down_sync(0xffffffffu, lsum, off);
    if ((tid & 31) == 0) ws[tid >> 5] = lsum;
    __syncthreads();
    if (tid == 0) {
        float t = 0.f;
#pragma unroll
        for (int w = 0; w < 8; w++) t += ws[w];
        g_part[blockIdx.x] = t;
    }
}

// ---------------------------------------------------------------------------
// Kernel 3: deterministic final loss reduction; loss = 1.25 * mean(d^2)
// ---------------------------------------------------------------------------
__global__ void finalize_kernel(float* __restrict__ out, int out_size)
{
    __shared__ float s[256];
    __shared__ float lossS;
    const int tid = threadIdx.x;
    float v = 0.f;
#pragma unroll
    for (int j = 0; j < 4; j++) v += g_part[tid + j * 256];
    s[tid] = v;
    __syncthreads();
    for (int o = 128; o > 0; o >>= 1) {
        if (tid < o) s[tid] += s[tid + o];
        __syncthreads();
    }
    if (tid == 0) lossS = s[0] * (1.25f / 8388608.0f);
    __syncthreads();
    for (int i = NTOT + tid; i < out_size; i += 256) out[i] = lossS;
}

// ---------------------------------------------------------------------------
extern "C" void kernel_launch(void* const* d_in, const int* in_sizes, int n_in,
                              void* d_out, int out_size)
{
    const float* z  = (const float*)d_in[0];
    const float* cb = (const float*)d_in[1];
    if (n_in >= 2 && in_sizes[0] == KCODES * C_DIM && in_sizes[1] == NTOT) {
        // defensive: swapped input order
        const float* t = z; z = cb; cb = t;
    }
    float* out = (float*)d_out;

    cnorm_kernel   <<<4,    256>>>(cb);
    znorm_kernel   <<<128,  256>>>(z);
    argmin_kernel  <<<512,  128>>>(z, cb);
    gather_kernel  <<<1024, 256>>>(z, cb, out);
    finalize_kernel<<<1,    256>>>(out, out_size);
}

// round 5
// speedup vs baseline: 2.1288x; 2.1265x over previous
#include <cuda_runtime.h>
#include <cuda_bf16.h>
#include <cstdint>

#define C_DIM   256
#define HW_DIM  1024
#define NVEC    32768
#define KCODES  1024
#define NTOT    8388608
#define CAND_CAP 64
#define MARGIN  6e-3f

// ---- pass-1 dynamic smem layout (bytes). Row pitch 528B = 264 halves = 132 words.
#define A_OFF    0            // A[128][264h]  = 67584
#define B0_OFF   67584        // B[128][264h]  = 67584
#define B1_OFF   135168       //                 67584
#define CN_OFF   202752       // f32[1024]     = 4096
#define ZNS_OFF  206848       // f32[128]
#define RMIN_OFF 207360       // u32[128]
#define RCNT_OFF 207872       // u32[128]
#define P1_SMEM  208384

// ---- gather dynamic smem layout
#define GZ_OFF    0           // zs[256][33] f32
#define GCB_OFF   33792       // cbs[32][257] f32
#define GIDX_OFF  66688
#define GWS_OFF   66816
#define G_SMEM    66848

__device__ float          g_cn[KCODES];
__device__ float          g_zn[NVEC];
__device__ float          g_part[1024];
__device__ unsigned int   g_ccnt[NVEC];
__device__ unsigned short g_cand[(size_t)NVEC * CAND_CAP];
__device__ uint4          g_cb16v[KCODES * C_DIM / 8];   // codebook bf16

// ---------------- helpers ----------------
__device__ __forceinline__ uint32_t smem_u32(const void* p) {
    uint32_t a;
    asm("{ .reg .u64 t; cvta.to.shared.u64 t, %1; cvt.u32.u64 %0, t; }" : "=r"(a) : "l"(p));
    return a;
}
#define CP_ASYNC16(dst, src) \
    asm volatile("cp.async.cg.shared.global [%0], [%1], 16;" :: "r"(dst), "l"(src) : "memory")
#define CP_COMMIT() asm volatile("cp.async.commit_group;" ::: "memory")
#define CP_WAIT0()  asm volatile("cp.async.wait_group 0;" ::: "memory")

__device__ __forceinline__ void mma16816(float* d, const uint32_t* a,
                                         uint32_t b0, uint32_t b1) {
    asm volatile(
        "mma.sync.aligned.m16n8k16.row.col.f32.bf16.bf16.f32 "
        "{%0,%1,%2,%3}, {%4,%5,%6,%7}, {%8,%9}, {%0,%1,%2,%3};"
        : "+f"(d[0]), "+f"(d[1]), "+f"(d[2]), "+f"(d[3])
        : "r"(a[0]), "r"(a[1]), "r"(a[2]), "r"(a[3]), "r"(b0), "r"(b1));
}
// order-preserving float<->uint for atomicMin
__device__ __forceinline__ uint32_t fenc(float f) {
    uint32_t u = __float_as_uint(f);
    return u ^ ((uint32_t)((int)u >> 31) | 0x80000000u);
}
__device__ __forceinline__ float fdec(uint32_t e) {
    uint32_t mask = ((uint32_t)((int)(~e) >> 31)) | 0x80000000u;
    return __uint_as_float(e ^ mask);
}

// ---------------- kernel 0a: codebook norms ----------------
__global__ void cnorm_kernel(const float* __restrict__ cb)
{
    int k = blockIdx.x * 256 + threadIdx.x;
    const float* row = cb + (size_t)k * C_DIM;
    float s = 0.f;
#pragma unroll 8
    for (int i = 0; i < C_DIM; i++) { float c = row[i]; s += c * c; }
    g_cn[k] = s;
}
// ---------------- kernel 0b: codebook -> bf16 ----------------
__global__ void cvt_cb_kernel(const float* __restrict__ cb)
{
    int i = blockIdx.x * 256 + threadIdx.x;
    ((__nv_bfloat16*)g_cb16v)[i] = __float2bfloat16(cb[i]);
}

// ---------------- pass 1: HMMA coarse scores + candidate filter ----------
// 256 CTAs x 128 rows. 8 warps: warp tile 32(M) x 64(N); chunks of 128 codes.
__global__ __launch_bounds__(256, 1)
void argmin_mma_kernel(const float* __restrict__ z)
{
    extern __shared__ char smem[];
    const uint32_t sb = smem_u32(smem);
    const uint32_t* Aw   = (const uint32_t*)smem;
    float*    cn_s = (float*)(smem + CN_OFF);
    float*    zns  = (float*)(smem + ZNS_OFF);
    uint32_t* rmin = (uint32_t*)(smem + RMIN_OFF);
    uint32_t* rcnt = (uint32_t*)(smem + RCNT_OFF);

    const int tid = threadIdx.x;
    const int rowBase = blockIdx.x * 128;
    const int b = rowBase >> 10, hw0 = rowBase & 1023;
    const float* zb = z + (size_t)b * (C_DIM * HW_DIM) + hw0;

    // prefetch B chunk 0 (threads 128..255, 32x16B lines each, coalesced)
    if (tid >= 128) {
        int t = tid - 128;
#pragma unroll
        for (int i = 0; i < 32; i++) {
            int idx = i * 128 + t;               // 4096 lines of 16B
            int k = idx >> 5, seg = idx & 31;
            const void* src = (const char*)g_cb16v + (((size_t)k * 32 + seg) << 4);
            CP_ASYNC16(sb + B0_OFF + (uint32_t)(k * 528 + seg * 16), src);
        }
        CP_COMMIT();
    }
    for (int i = tid; i < KCODES; i += 256) cn_s[i] = g_cn[i];
    if (tid < 128) { rmin[tid] = 0xFFFFFFFFu; rcnt[tid] = 0u; }

    // A fill + zn (thread r = row; zn sequential ascending c — R2-validated order)
    if (tid < 128) {
        const int r = tid;
        float zn = 0.f;
        for (int c0 = 0; c0 < C_DIM; c0 += 8) {
            float v[8];
#pragma unroll
            for (int u = 0; u < 8; u++) v[u] = zb[(size_t)(c0 + u) * HW_DIM + r];
#pragma unroll
            for (int u = 0; u < 8; u++) zn = fmaf(v[u], v[u], zn);
            uint32_t pk[4];
#pragma unroll
            for (int q = 0; q < 4; q++) {
                __nv_bfloat162 h = __floats2bfloat162_rn(v[2 * q], v[2 * q + 1]);
                pk[q] = *(uint32_t*)&h;
            }
            *(uint4*)(smem + A_OFF + r * 528 + c0 * 2) = make_uint4(pk[0], pk[1], pk[2], pk[3]);
        }
        zns[r] = zn;
        g_zn[rowBase + r] = zn;
    }
    CP_WAIT0();
    __syncthreads();

    const int wid = tid >> 5, lane = tid & 31;
    const int m0 = (wid >> 1) * 32, n0 = (wid & 1) * 64;
    const int quad = lane >> 2, qt = lane & 3;

    for (int c = 0; c < 8; c++) {
        const int cur = c & 1;
        // prefetch next chunk into other buffer (overlaps with mma below)
        if (c + 1 < 8) {
            const int k0n = (c + 1) * 128;
            const uint32_t boff = cur ? B0_OFF : B1_OFF;
#pragma unroll
            for (int i = 0; i < 16; i++) {
                int idx = i * 256 + tid;
                int k = idx >> 5, seg = idx & 31;
                const void* src = (const char*)g_cb16v + (((size_t)(k0n + k) * 32 + seg) << 4);
                CP_ASYNC16(sb + boff + (uint32_t)(k * 528 + seg * 16), src);
            }
            CP_COMMIT();
        }

        // ---- MMA: warp tile 32x64, 16 k-steps of k16
        const uint32_t* Bw = (const uint32_t*)(smem + (cur ? B1_OFF : B0_OFF));
        float acc[2][8][4];
#pragma unroll
        for (int mt = 0; mt < 2; mt++)
#pragma unroll
            for (int nt = 0; nt < 8; nt++)
#pragma unroll
                for (int q = 0; q < 4; q++) acc[mt][nt][q] = 0.f;

#pragma unroll
        for (int ks = 0; ks < 16; ks++) {
            const int wb = ks * 8 + qt;          // word offset within row
            uint32_t a[2][4];
#pragma unroll
            for (int mt = 0; mt < 2; mt++) {
                const uint32_t* ap = Aw + (m0 + mt * 16 + quad) * 132 + wb;
                a[mt][0] = ap[0];
                a[mt][1] = ap[8 * 132];
                a[mt][2] = ap[4];
                a[mt][3] = ap[8 * 132 + 4];
            }
#pragma unroll
            for (int nt = 0; nt < 8; nt++) {
                const uint32_t* bp = Bw + (n0 + nt * 8 + quad) * 132 + wb;
                uint32_t b0 = bp[0], b1 = bp[4];
#pragma unroll
                for (int mt = 0; mt < 2; mt++) mma16816(acc[mt][nt], a[mt], b0, b1);
            }
        }

        // ---- phase 1: coarse distances + per-row running min
        const int kchunk = c * 128;
#pragma unroll
        for (int mt = 0; mt < 2; mt++) {
            const int r_lo = m0 + mt * 16 + quad, r_hi = r_lo + 8;
            const float zlo = zns[r_lo], zhi = zns[r_hi];
            float mn_lo = 3.4e38f, mn_hi = 3.4e38f;
#pragma unroll
            for (int nt = 0; nt < 8; nt++) {
                const int k = kchunk + n0 + nt * 8 + qt * 2;
                float d00 = fmaf(-2.f, acc[mt][nt][0], zlo) + cn_s[k];
                float d01 = fmaf(-2.f, acc[mt][nt][1], zlo) + cn_s[k + 1];
                float d10 = fmaf(-2.f, acc[mt][nt][2], zhi) + cn_s[k];
                float d11 = fmaf(-2.f, acc[mt][nt][3], zhi) + cn_s[k + 1];
                acc[mt][nt][0] = d00; acc[mt][nt][1] = d01;
                acc[mt][nt][2] = d10; acc[mt][nt][3] = d11;
                mn_lo = fminf(mn_lo, fminf(d00, d01));
                mn_hi = fminf(mn_hi, fminf(d10, d11));
            }
            atomicMin(&rmin[r_lo], fenc(mn_lo));
            atomicMin(&rmin[r_hi], fenc(mn_hi));
        }
        __syncthreads();

        // ---- phase 2: collect candidates below rmin+margin (superset-safe)
#pragma unroll
        for (int mt = 0; mt < 2; mt++) {
            const int r_lo = m0 + mt * 16 + quad, r_hi = r_lo + 8;
            const float th_lo = fdec(rmin[r_lo]) + MARGIN;
            const float th_hi = fdec(rmin[r_hi]) + MARGIN;
#pragma unroll
            for (int nt = 0; nt < 8; nt++) {
                const int k = kchunk + n0 + nt * 8 + qt * 2;
                if (acc[mt][nt][0] < th_lo) {
                    unsigned s = atomicAdd(&rcnt[r_lo], 1u);
                    if (s < CAND_CAP) g_cand[(size_t)(rowBase + r_lo) * CAND_CAP + s] = (unsigned short)k;
                }
                if (acc[mt][nt][1] < th_lo) {
                    unsigned s = atomicAdd(&rcnt[r_lo], 1u);
                    if (s < CAND_CAP) g_cand[(size_t)(rowBase + r_lo) * CAND_CAP + s] = (unsigned short)(k + 1);
                }
                if (acc[mt][nt][2] < th_hi) {
                    unsigned s = atomicAdd(&rcnt[r_hi], 1u);
                    if (s < CAND_CAP) g_cand[(size_t)(rowBase + r_hi) * CAND_CAP + s] = (unsigned short)k;
                }
                if (acc[mt][nt][3] < th_hi) {
                    unsigned s = atomicAdd(&rcnt[r_hi], 1u);
                    if (s < CAND_CAP) g_cand[(size_t)(rowBase + r_hi) * CAND_CAP + s] = (unsigned short)(k + 1);
                }
            }
        }
        CP_WAIT0();
        __syncthreads();   // next B ready; phase-2 reads of rmin done before next chunk
    }
    if (tid < 128) g_ccnt[rowBase + tid] = rcnt[tid];
}

// ---------------- pass 2: exact refine + gather + loss ----------------
__global__ __launch_bounds__(256)
void gather2_kernel(const float* __restrict__ z, const float* __restrict__ cb,
                    float* __restrict__ out)
{
    extern __shared__ char smem[];
    float* zs    = (float*)(smem + GZ_OFF);
    float* cbs   = (float*)(smem + GCB_OFF);
    int*   idx_s = (int*)(smem + GIDX_OFF);
    float* ws    = (float*)(smem + GWS_OFF);

    const int tid = threadIdx.x;
    const int v0 = blockIdx.x * 32;
    const int b = v0 >> 10, hw0 = v0 & 1023;
    const size_t base = (size_t)b * (C_DIM * HW_DIM) + hw0;

    // A: z tile -> smem (only global z read here)
#pragma unroll 4
    for (int it = 0; it < 32; it++) {
        int u = it * 256 + tid;
        int c = u >> 5, m = u & 31;
        zs[c * 33 + m] = z[base + ((size_t)c << 10) + m];
    }
    __syncthreads();

    // B: exact fp32 refinement (warp w -> rows 4w..4w+3); candidates unordered,
    //    so ties resolved by (d, k) with lower-k preference (jnp.argmin rule).
    const int w = tid >> 5, lane = tid & 31;
#pragma unroll
    for (int j = 0; j < 4; j++) {
        int m = w * 4 + j;
        int n = v0 + m;
        float zn = g_zn[n];
        unsigned cnt = g_ccnt[n];
        float bd = 3.4e38f; int bk = 0x7fffffff;
        bool full = (cnt > CAND_CAP);
        unsigned lim = full ? (unsigned)KCODES : cnt;
        for (unsigned i = 0; i < lim; i++) {
            int k = full ? (int)i : (int)g_cand[(size_t)n * CAND_CAP + i];
            float ps = 0.f;
#pragma unroll
            for (int u = 0; u < 8; u++) {
                int c = lane + 32 * u;
                ps = fmaf(zs[c * 33 + m], __ldg(&cb[(size_t)k * C_DIM + c]), ps);
            }
#pragma unroll
            for (int o = 16; o; o >>= 1) ps += __shfl_xor_sync(0xffffffffu, ps, o);
            float d = fmaf(-2.f, ps, zn) + g_cn[k];  // reference rounding pipeline
            if (d < bd || (d == bd && k < bk)) { bd = d; bk = k; }
        }
        if (lane == 0) idx_s[m] = bk;
    }
    __syncthreads();

    // C: gather chosen codebook rows (coalesced)
#pragma unroll 4
    for (int i = 0; i < 32; i++)
        cbs[i * 257 + tid] = cb[(size_t)idx_s[i] * C_DIM + tid];
    __syncthreads();

    // D: output + loss partials (arithmetic identical to R2)
    float lsum = 0.f;
#pragma unroll 4
    for (int it = 0; it < 32; it++) {
        int u = it * 256 + tid;
        int m = u & 31, c = u >> 5;
        float q  = cbs[m * 257 + c];
        float zv = zs[c * 33 + m];
        float d  = q - zv;
        out[base + ((size_t)c << 10) + m] = zv + d;
        lsum += d * d;
    }
#pragma unroll
    for (int off = 16; off; off >>= 1)
        lsum += __shfl_down_sync(0xffffffffu, lsum, off);
    if ((tid & 31) == 0) ws[tid >> 5] = lsum;
    __syncthreads();
    if (tid == 0) {
        float t = 0.f;
#pragma unroll
        for (int q = 0; q < 8; q++) t += ws[q];
        g_part[blockIdx.x] = t;
    }
}

// ---------------- kernel 3: final loss ----------------
__global__ void finalize_kernel(float* __restrict__ out, int out_size)
{
    __shared__ float s[256];
    __shared__ float lossS;
    const int tid = threadIdx.x;
    float v = 0.f;
#pragma unroll
    for (int j = 0; j < 4; j++) v += g_part[tid + j * 256];
    s[tid] = v;
    __syncthreads();
    for (int o = 128; o > 0; o >>= 1) {
        if (tid < o) s[tid] += s[tid + o];
        __syncthreads();
    }
    if (tid == 0) lossS = s[0] * (1.25f / 8388608.0f);
    __syncthreads();
    for (int i = NTOT + tid; i < out_size; i += 256) out[i] = lossS;
}

// ---------------------------------------------------------------------------
extern "C" void kernel_launch(void* const* d_in, const int* in_sizes, int n_in,
                              void* d_out, int out_size)
{
    const float* z  = (const float*)d_in[0];
    const float* cb = (const float*)d_in[1];
    if (n_in >= 2 && in_sizes[0] == KCODES * C_DIM && in_sizes[1] == NTOT) {
        const float* t = z; z = cb; cb = t;
    }
    float* out = (float*)d_out;

    cudaFuncSetAttribute(argmin_mma_kernel,
                         cudaFuncAttributeMaxDynamicSharedMemorySize, P1_SMEM);
    cudaFuncSetAttribute(gather2_kernel,
                         cudaFuncAttributeMaxDynamicSharedMemorySize, G_SMEM);

    cnorm_kernel    <<<4,    256>>>(cb);
    cvt_cb_kernel   <<<1024, 256>>>(cb);
    argmin_mma_kernel<<<256, 256, P1_SMEM>>>(z);
    gather2_kernel  <<<1024, 256, G_SMEM>>>(z, cb, out);
    finalize_kernel <<<1,    256>>>(out, out_size);
}

// round 6
// speedup vs baseline: 2.5822x; 1.2130x over previous
#include <cuda_runtime.h>
#include <cuda_bf16.h>
#include <cstdint>

#define C_DIM   256
#define HW_DIM  1024
#define NVEC    32768
#define KCODES  1024
#define NTOT    8388608
#define CAND_CAP 64
#define MARGIN  6e-3f

// ---- pass-1 dynamic smem layout (bytes). Row pitch 528B = 264 halves = 132 words.
#define A_OFF    0            // A[128][264h]  = 67584
#define B0_OFF   67584        // B[128][264h]  = 67584
#define B1_OFF   135168
#define CN_OFF   202752       // f32[1024]
#define ZNS_OFF  206848       // f32[128]
#define RMIN_OFF 207360       // u32[128]
#define RCNT_OFF 207872       // u32[128]
#define P1_SMEM  208384

// ---- gather dynamic smem layout
#define GZ_OFF    0           // zs[256][33] f32
#define GCB_OFF   33792       // cbs[32][257] f32
#define GIDX_OFF  66688
#define GWS_OFF   66816
#define G_SMEM    66848

__device__ float          g_cn[KCODES];
__device__ float          g_zn[NVEC];
__device__ float          g_part[1024];
__device__ unsigned int   g_ccnt[NVEC];
__device__ unsigned short g_cand[(size_t)NVEC * CAND_CAP];
__device__ uint4          g_cb16v[KCODES * C_DIM / 8];   // codebook bf16

// ---------------- helpers ----------------
__device__ __forceinline__ uint32_t smem_u32(const void* p) {
    uint32_t a;
    asm("{ .reg .u64 t; cvta.to.shared.u64 t, %1; cvt.u32.u64 %0, t; }" : "=r"(a) : "l"(p));
    return a;
}
#define CP_ASYNC16(dst, src) \
    asm volatile("cp.async.cg.shared.global [%0], [%1], 16;" :: "r"(dst), "l"(src) : "memory")
#define CP_COMMIT() asm volatile("cp.async.commit_group;" ::: "memory")
#define CP_WAIT0()  asm volatile("cp.async.wait_group 0;" ::: "memory")

__device__ __forceinline__ void mma16816(float* d, const uint32_t* a,
                                         uint32_t b0, uint32_t b1) {
    asm volatile(
        "mma.sync.aligned.m16n8k16.row.col.f32.bf16.bf16.f32 "
        "{%0,%1,%2,%3}, {%4,%5,%6,%7}, {%8,%9}, {%0,%1,%2,%3};"
        : "+f"(d[0]), "+f"(d[1]), "+f"(d[2]), "+f"(d[3])
        : "r"(a[0]), "r"(a[1]), "r"(a[2]), "r"(a[3]), "r"(b0), "r"(b1));
}
// order-preserving float<->uint for atomicMin
__device__ __forceinline__ uint32_t fenc(float f) {
    uint32_t u = __float_as_uint(f);
    return u ^ ((uint32_t)((int)u >> 31) | 0x80000000u);
}
__device__ __forceinline__ float fdec(uint32_t e) {
    uint32_t mask = ((uint32_t)((int)(~e) >> 31)) | 0x80000000u;
    return __uint_as_float(e ^ mask);
}

// ---------------- kernel 0a: codebook norms (validated order — DO NOT CHANGE) --
__global__ void cnorm_kernel(const float* __restrict__ cb)
{
    int k = blockIdx.x * 256 + threadIdx.x;
    const float* row = cb + (size_t)k * C_DIM;
    float s = 0.f;
#pragma unroll 8
    for (int i = 0; i < C_DIM; i++) { float c = row[i]; s += c * c; }
    g_cn[k] = s;
}
// ---------------- kernel 0b: codebook -> bf16 ----------------
__global__ void cvt_cb_kernel(const float* __restrict__ cb)
{
    int i = blockIdx.x * 256 + threadIdx.x;
    ((__nv_bfloat16*)g_cb16v)[i] = __float2bfloat16(cb[i]);
}

// ---------------- pass 1: HMMA coarse scores + candidate filter ----------
// 256 CTAs x 128 rows. 16 warps: warp tile 16(M) x 64(N); 8 chunks of 128 codes.
// A fragments hoisted into registers once (A reused across all chunks).
__global__ __launch_bounds__(512, 1)
void argmin_mma_kernel(const float* __restrict__ z)
{
    extern __shared__ char smem[];
    const uint32_t sb = smem_u32(smem);
    const uint32_t* Aw = (const uint32_t*)smem;
    float*    cn_s = (float*)(smem + CN_OFF);
    float*    zns  = (float*)(smem + ZNS_OFF);
    uint32_t* rmin = (uint32_t*)(smem + RMIN_OFF);
    uint32_t* rcnt = (uint32_t*)(smem + RCNT_OFF);

    const int tid = threadIdx.x;
    const int rowBase = blockIdx.x * 128;
    const int b = rowBase >> 10, hw0 = rowBase & 1023;
    const float* zb = z + (size_t)b * (C_DIM * HW_DIM) + hw0;

    // ---- prologue partition:
    //   threads 0-127   : A fill + zn (sequential ascending c — R2-validated order)
    //   threads 128-255 : cn tile + rmin/rcnt init
    //   threads 256-511 : prefetch B chunk 0 (16 x 16B lines each, coalesced)
    if (tid >= 256) {
        int t = tid - 256;
#pragma unroll
        for (int i = 0; i < 16; i++) {
            int idx = i * 256 + t;               // 4096 lines of 16B
            int k = idx >> 5, seg = idx & 31;
            const void* src = (const char*)g_cb16v + (((size_t)k * 32 + seg) << 4);
            CP_ASYNC16(sb + B0_OFF + (uint32_t)(k * 528 + seg * 16), src);
        }
        CP_COMMIT();
    } else if (tid >= 128) {
        int t = tid - 128;
#pragma unroll
        for (int i = 0; i < 8; i++) cn_s[t + i * 128] = g_cn[t + i * 128];
        rmin[t] = 0xFFFFFFFFu; rcnt[t] = 0u;
    } else {
        const int r = tid;
        float zn = 0.f;
        for (int c0 = 0; c0 < C_DIM; c0 += 8) {
            float v[8];
#pragma unroll
            for (int u = 0; u < 8; u++) v[u] = zb[(size_t)(c0 + u) * HW_DIM + r];
#pragma unroll
            for (int u = 0; u < 8; u++) zn = fmaf(v[u], v[u], zn);
            uint32_t pk[4];
#pragma unroll
            for (int q = 0; q < 4; q++) {
                __nv_bfloat162 h = __floats2bfloat162_rn(v[2 * q], v[2 * q + 1]);
                pk[q] = *(uint32_t*)&h;
            }
            *(uint4*)(smem + A_OFF + r * 528 + c0 * 2) = make_uint4(pk[0], pk[1], pk[2], pk[3]);
        }
        zns[r] = zn;
        g_zn[rowBase + r] = zn;
    }
    CP_WAIT0();
    __syncthreads();

    const int wid = tid >> 5, lane = tid & 31;
    const int m0 = (wid >> 1) * 16, n0 = (wid & 1) * 64;
    const int quad = lane >> 2, qt = lane & 3;
    const int r_lo = m0 + quad, r_hi = r_lo + 8;

    // ---- hoist A fragments (identical mapping to the R5-validated one)
    uint32_t af[16][4];
#pragma unroll
    for (int ks = 0; ks < 16; ks++) {
        const uint32_t* ap = Aw + r_lo * 132 + ks * 8 + qt;
        af[ks][0] = ap[0];
        af[ks][1] = ap[8 * 132];
        af[ks][2] = ap[4];
        af[ks][3] = ap[8 * 132 + 4];
    }
    const float zlo = zns[r_lo], zhi = zns[r_hi];

    for (int c = 0; c < 8; c++) {
        const int cur = c & 1;
        // prefetch next chunk into other buffer (overlaps the mma below)
        if (c + 1 < 8) {
            const int k0n = (c + 1) * 128;
            const uint32_t boff = cur ? B0_OFF : B1_OFF;
#pragma unroll
            for (int i = 0; i < 8; i++) {
                int idx = i * 512 + tid;
                int k = idx >> 5, seg = idx & 31;
                const void* src = (const char*)g_cb16v + (((size_t)(k0n + k) * 32 + seg) << 4);
                CP_ASYNC16(sb + boff + (uint32_t)(k * 528 + seg * 16), src);
            }
            CP_COMMIT();
        }

        // ---- MMA: warp tile 16x64, 16 k-steps of k16 (B loads only; A in regs)
        const uint32_t* Bw = (const uint32_t*)(smem + (cur ? B1_OFF : B0_OFF));
        float acc[8][4];
#pragma unroll
        for (int nt = 0; nt < 8; nt++)
#pragma unroll
            for (int q = 0; q < 4; q++) acc[nt][q] = 0.f;

#pragma unroll
        for (int ks = 0; ks < 16; ks++) {
            const int wb = ks * 8 + qt;
#pragma unroll
            for (int nt = 0; nt < 8; nt++) {
                const uint32_t* bp = Bw + (n0 + nt * 8 + quad) * 132 + wb;
                mma16816(acc[nt], af[ks], bp[0], bp[4]);
            }
        }

        // ---- phase 1: coarse distances + per-row running min
        const int kchunk = c * 128;
        float mn_lo = 3.4e38f, mn_hi = 3.4e38f;
#pragma unroll
        for (int nt = 0; nt < 8; nt++) {
            const int k = kchunk + n0 + nt * 8 + qt * 2;
            float d00 = fmaf(-2.f, acc[nt][0], zlo) + cn_s[k];
            float d01 = fmaf(-2.f, acc[nt][1], zlo) + cn_s[k + 1];
            float d10 = fmaf(-2.f, acc[nt][2], zhi) + cn_s[k];
            float d11 = fmaf(-2.f, acc[nt][3], zhi) + cn_s[k + 1];
            acc[nt][0] = d00; acc[nt][1] = d01;
            acc[nt][2] = d10; acc[nt][3] = d11;
            mn_lo = fminf(mn_lo, fminf(d00, d01));
            mn_hi = fminf(mn_hi, fminf(d10, d11));
        }
        atomicMin(&rmin[r_lo], fenc(mn_lo));
        atomicMin(&rmin[r_hi], fenc(mn_hi));
        __syncthreads();

        // ---- phase 2: collect candidates below rmin+margin (superset-safe)
        const float th_lo = fdec(rmin[r_lo]) + MARGIN;
        const float th_hi = fdec(rmin[r_hi]) + MARGIN;
#pragma unroll
        for (int nt = 0; nt < 8; nt++) {
            const int k = kchunk + n0 + nt * 8 + qt * 2;
            if (acc[nt][0] < th_lo) {
                unsigned s = atomicAdd(&rcnt[r_lo], 1u);
                if (s < CAND_CAP) g_cand[(size_t)(rowBase + r_lo) * CAND_CAP + s] = (unsigned short)k;
            }
            if (acc[nt][1] < th_lo) {
                unsigned s = atomicAdd(&rcnt[r_lo], 1u);
                if (s < CAND_CAP) g_cand[(size_t)(rowBase + r_lo) * CAND_CAP + s] = (unsigned short)(k + 1);
            }
            if (acc[nt][2] < th_hi) {
                unsigned s = atomicAdd(&rcnt[r_hi], 1u);
                if (s < CAND_CAP) g_cand[(size_t)(rowBase + r_hi) * CAND_CAP + s] = (unsigned short)k;
            }
            if (acc[nt][3] < th_hi) {
                unsigned s = atomicAdd(&rcnt[r_hi], 1u);
                if (s < CAND_CAP) g_cand[(size_t)(rowBase + r_hi) * CAND_CAP + s] = (unsigned short)(k + 1);
            }
        }
        CP_WAIT0();
        __syncthreads();
    }
    if (tid < 128) g_ccnt[rowBase + tid] = rcnt[tid];
}

// ---------------- pass 2: exact refine (ILP-4) + gather + loss ----------------
__global__ __launch_bounds__(256)
void gather2_kernel(const float* __restrict__ z, const float* __restrict__ cb,
                    float* __restrict__ out)
{
    extern __shared__ char smem[];
    float* zs    = (float*)(smem + GZ_OFF);
    float* cbs   = (float*)(smem + GCB_OFF);
    int*   idx_s = (int*)(smem + GIDX_OFF);
    float* ws    = (float*)(smem + GWS_OFF);

    const int tid = threadIdx.x;
    const int v0 = blockIdx.x * 32;
    const int b = v0 >> 10, hw0 = v0 & 1023;
    const size_t base = (size_t)b * (C_DIM * HW_DIM) + hw0;

    // A: z tile -> smem (only global z read here)
#pragma unroll 4
    for (int it = 0; it < 32; it++) {
        int u = it * 256 + tid;
        int c = u >> 5, m = u & 31;
        zs[c * 33 + m] = z[base + ((size_t)c << 10) + m];
    }
    __syncthreads();

    // B: exact fp32 refinement, 4 candidates in flight (latency hiding).
    //    z row cached in registers; ties resolved by (d, k), lower k wins.
    const int w = tid >> 5, lane = tid & 31;
#pragma unroll
    for (int j = 0; j < 4; j++) {
        int m = w * 4 + j;
        int n = v0 + m;
        float zn = g_zn[n];
        unsigned cnt = g_ccnt[n];
        bool full = (cnt > CAND_CAP);
        unsigned lim = full ? (unsigned)KCODES : cnt;
        float zv[8];
#pragma unroll
        for (int u = 0; u < 8; u++) zv[u] = zs[(lane + 32 * u) * 33 + m];
        float bd = 3.4e38f; int bk = 0x7fffffff;
        for (unsigned i = 0; i < lim; i += 4) {
            int kk[4];
#pragma unroll
            for (int t = 0; t < 4; t++) {
                unsigned ii = i + t; if (ii >= lim) ii = lim - 1;  // pad: duplicate
                kk[t] = full ? (int)ii : (int)g_cand[(size_t)n * CAND_CAP + ii];
            }
            float ps[4] = {0.f, 0.f, 0.f, 0.f};
#pragma unroll
            for (int u = 0; u < 8; u++) {
                int c = lane + 32 * u;
#pragma unroll
                for (int t = 0; t < 4; t++)
                    ps[t] = fmaf(zv[u], __ldg(&cb[(size_t)kk[t] * C_DIM + c]), ps[t]);
            }
#pragma unroll
            for (int o = 16; o; o >>= 1)
#pragma unroll
                for (int t = 0; t < 4; t++)
                    ps[t] += __shfl_xor_sync(0xffffffffu, ps[t], o);
#pragma unroll
            for (int t = 0; t < 4; t++) {
                float d = fmaf(-2.f, ps[t], zn) + g_cn[kk[t]];  // reference rounding
                if (d < bd || (d == bd && kk[t] < bk)) { bd = d; bk = kk[t]; }
            }
        }
        if (lane == 0) idx_s[m] = bk;
    }
    __syncthreads();

    // C: gather chosen codebook rows (coalesced)
#pragma unroll 4
    for (int i = 0; i < 32; i++)
        cbs[i * 257 + tid] = cb[(size_t)idx_s[i] * C_DIM + tid];
    __syncthreads();

    // D: output + loss partials (arithmetic identical to R2)
    float lsum = 0.f;
#pragma unroll 4
    for (int it = 0; it < 32; it++) {
        int u = it * 256 + tid;
        int m = u & 31, c = u >> 5;
        float q  = cbs[m * 257 + c];
        float zv = zs[c * 33 + m];
        float d  = q - zv;
        out[base + ((size_t)c << 10) + m] = zv + d;
        lsum += d * d;
    }
#pragma unroll
    for (int off = 16; off; off >>= 1)
        lsum += __shfl_down_sync(0xffffffffu, lsum, off);
    if ((tid & 31) == 0) ws[tid >> 5] = lsum;
    __syncthreads();
    if (tid == 0) {
        float t = 0.f;
#pragma unroll
        for (int q = 0; q < 8; q++) t += ws[q];
        g_part[blockIdx.x] = t;
    }
}

// ---------------- kernel 3: final loss ----------------
__global__ void finalize_kernel(float* __restrict__ out, int out_size)
{
    __shared__ float s[256];
    __shared__ float lossS;
    const int tid = threadIdx.x;
    float v = 0.f;
#pragma unroll
    for (int j = 0; j < 4; j++) v += g_part[tid + j * 256];
    s[tid] = v;
    __syncthreads();
    for (int o = 128; o > 0; o >>= 1) {
        if (tid < o) s[tid] += s[tid + o];
        __syncthreads();
    }
    if (tid == 0) lossS = s[0] * (1.25f / 8388608.0f);
    __syncthreads();
    for (int i = NTOT + tid; i < out_size; i += 256) out[i] = lossS;
}

// ---------------------------------------------------------------------------
extern "C" void kernel_launch(void* const* d_in, const int* in_sizes, int n_in,
                              void* d_out, int out_size)
{
    const float* z  = (const float*)d_in[0];
    const float* cb = (const float*)d_in[1];
    if (n_in >= 2 && in_sizes[0] == KCODES * C_DIM && in_sizes[1] == NTOT) {
        const float* t = z; z = cb; cb = t;
    }
    float* out = (float*)d_out;

    cudaFuncSetAttribute(argmin_mma_kernel,
                         cudaFuncAttributeMaxDynamicSharedMemorySize, P1_SMEM);
    cudaFuncSetAttribute(gather2_kernel,
                         cudaFuncAttributeMaxDynamicSharedMemorySize, G_SMEM);

    cnorm_kernel     <<<4,    256>>>(cb);
    cvt_cb_kernel    <<<1024, 256>>>(cb);
    argmin_mma_kernel<<<256,  512, P1_SMEM>>>(z);
    gather2_kernel   <<<1024, 256, G_SMEM>>>(z, cb, out);
    finalize_kernel  <<<1,    256>>>(out, out_size);
}